// round 2
// baseline (speedup 1.0000x reference)
#include <cuda_runtime.h>

#define NN 50000
#define EE 800000

// Scratch (no cudaMalloc allowed)
__device__ float g_ht[NN * 128];   // h @ W_node, [N][H*F]
__device__ float g_ss[NN * 8];     // per-node src attention scalar, [N][H]
__device__ float g_sd[NN * 8];     // per-node dst attention scalar, [N][H]
__device__ float g_se[NN * 8];     // sum of exp per (dst, head)

__device__ __forceinline__ void red_add_v4(float* p, float4 v) {
    asm volatile("red.global.add.v4.f32 [%0], {%1,%2,%3,%4};"
                 :: "l"(p), "f"(v.x), "f"(v.y), "f"(v.z), "f"(v.w)
                 : "memory");
}

// ---------------------------------------------------------------------------
// K1: h_trans = h @ W_node.  W (128x128 fp32 = 64KB) cached in SMEM.
// Tile: 32 nodes x 128 outputs. Thread: 4 nodes x 4 outputs (float4).
// ---------------------------------------------------------------------------
__global__ __launch_bounds__(256, 2) void k_gemm(const float* __restrict__ hin,
                                                 const float* __restrict__ Wn) {
    extern __shared__ float sm[];
    float4* Wsh = (float4*)sm;            // [128][32] float4 = 64KB
    float*  hsh = sm + 128 * 128;         // [32][128] floats = 16KB

    const int tid = threadIdx.x;
    const float4* Wg = (const float4*)Wn;
#pragma unroll
    for (int i = 0; i < 16; i++) Wsh[tid + i * 256] = Wg[tid + i * 256];

    const int tx = tid & 31;    // column group: cols 4*tx .. 4*tx+3
    const int ty = tid >> 5;    // node group:   rows ty*4 .. ty*4+3
    const int ntiles = (NN + 31) >> 5;

    for (int tile = blockIdx.x; tile < ntiles; tile += gridDim.x) {
        const int n0 = tile << 5;
        __syncthreads();  // protect hsh (and Wsh on first iter)
#pragma unroll
        for (int i = 0; i < 4; i++) {
            int idx = tid + i * 256;          // float4 index, == r*32+c
            int r = idx >> 5, c = idx & 31;
            float4 v = make_float4(0.f, 0.f, 0.f, 0.f);
            if (n0 + r < NN) v = ((const float4*)hin)[(size_t)(n0 + r) * 32 + c];
            ((float4*)hsh)[idx] = v;
        }
        __syncthreads();

        float4 a0 = make_float4(0.f, 0.f, 0.f, 0.f);
        float4 a1 = a0, a2 = a0, a3 = a0;
#pragma unroll 8
        for (int k = 0; k < 128; k++) {
            float4 w = Wsh[k * 32 + tx];
            float h0 = hsh[(ty * 4 + 0) * 128 + k];
            float h1 = hsh[(ty * 4 + 1) * 128 + k];
            float h2 = hsh[(ty * 4 + 2) * 128 + k];
            float h3 = hsh[(ty * 4 + 3) * 128 + k];
            a0.x += h0 * w.x; a0.y += h0 * w.y; a0.z += h0 * w.z; a0.w += h0 * w.w;
            a1.x += h1 * w.x; a1.y += h1 * w.y; a1.z += h1 * w.z; a1.w += h1 * w.w;
            a2.x += h2 * w.x; a2.y += h2 * w.y; a2.z += h2 * w.z; a2.w += h2 * w.w;
            a3.x += h3 * w.x; a3.y += h3 * w.y; a3.z += h3 * w.z; a3.w += h3 * w.w;
        }
        float4* op = (float4*)g_ht;
        int n;
        n = n0 + ty * 4 + 0; if (n < NN) op[n * 32 + tx] = a0;
        n = n0 + ty * 4 + 1; if (n < NN) op[n * 32 + tx] = a1;
        n = n0 + ty * 4 + 2; if (n < NN) op[n * 32 + tx] = a2;
        n = n0 + ty * 4 + 3; if (n < NN) op[n * 32 + tx] = a3;
    }
}

// ---------------------------------------------------------------------------
// K2: per-node attention scalars: s_src[n,h] = <h_trans[n,h,:], a_src[h,:]>
// ---------------------------------------------------------------------------
__global__ void k_sdot(const float* __restrict__ asrc,
                       const float* __restrict__ adst) {
    int t = blockIdx.x * blockDim.x + threadIdx.x;
    if (t >= NN * 8) return;
    int n = t >> 3, hh = t & 7;
    const float4* hp = (const float4*)(g_ht + (size_t)n * 128 + hh * 16);
    const float4* as = (const float4*)(asrc + hh * 16);
    const float4* ad = (const float4*)(adst + hh * 16);
    float ss = 0.f, sd = 0.f;
#pragma unroll
    for (int i = 0; i < 4; i++) {
        float4 v = hp[i];
        float4 a = as[i];
        float4 b = ad[i];
        ss += v.x * a.x + v.y * a.y + v.z * a.z + v.w * a.w;
        sd += v.x * b.x + v.y * b.y + v.z * b.z + v.w * b.w;
    }
    g_ss[t] = ss;
    g_sd[t] = sd;
}

// ---------------------------------------------------------------------------
// K3: edge pass A — accumulate sum of exp(leaky_relu(logit)) per (dst, head).
// One thread per edge; 2x red.v4 atomics.
// (No segment-max: logits are bounded ~|12|, exp cannot overflow fp32, and
//  softmax is shift-invariant.)
// ---------------------------------------------------------------------------
__global__ void k_edgeA(const int* __restrict__ ei,
                        const float* __restrict__ ef,
                        const float* __restrict__ We) {
    int e = blockIdx.x * 256 + threadIdx.x;   // grid sized exactly: EE % 256 == 0
    int src = ei[e];
    int dst = ei[EE + e];
    float f = __ldg(ef + e);
    float4 s0 = ((const float4*)g_ss)[src * 2];
    float4 s1 = ((const float4*)g_ss)[src * 2 + 1];
    float4 d0 = ((const float4*)g_sd)[dst * 2];
    float4 d1 = ((const float4*)g_sd)[dst * 2 + 1];
    float a[8];
    a[0] = s0.x + d0.x + f * __ldg(We + 0);
    a[1] = s0.y + d0.y + f * __ldg(We + 1);
    a[2] = s0.z + d0.z + f * __ldg(We + 2);
    a[3] = s0.w + d0.w + f * __ldg(We + 3);
    a[4] = s1.x + d1.x + f * __ldg(We + 4);
    a[5] = s1.y + d1.y + f * __ldg(We + 5);
    a[6] = s1.z + d1.z + f * __ldg(We + 6);
    a[7] = s1.w + d1.w + f * __ldg(We + 7);
#pragma unroll
    for (int i = 0; i < 8; i++) {
        float x = a[i];
        x = x > 0.f ? x : 0.2f * x;
        a[i] = __expf(x);
    }
    red_add_v4(g_se + dst * 8,     make_float4(a[0], a[1], a[2], a[3]));
    red_add_v4(g_se + dst * 8 + 4, make_float4(a[4], a[5], a[6], a[7]));
}

// ---------------------------------------------------------------------------
// K4: edge pass B — alpha = exp/sumexp (x 1/8 for head-mean folded in),
// gather src features, scatter weighted message into out[dst].
// 8 threads per edge: lane l owns head l's alpha; lanes split (head-half, quad)
// for the feature accumulation; 4x red.v4 per edge.
// ---------------------------------------------------------------------------
__global__ void k_edgeB(const int* __restrict__ ei,
                        const float* __restrict__ ef,
                        const float* __restrict__ We,
                        float* __restrict__ out) {
    int gid = blockIdx.x * 256 + threadIdx.x;  // grid exact: (EE*8) % 256 == 0
    int e = gid >> 3;
    int l = gid & 7;
    int src = ei[e];
    int dst = ei[EE + e];
    float f = __ldg(ef + e);
    float s = g_ss[src * 8 + l] + g_sd[dst * 8 + l] + f * __ldg(We + l);
    s = s > 0.f ? s : 0.2f * s;
    float alpha = 0.125f * __expf(s) / g_se[dst * 8 + l];

    int q = l & 3;        // feature quad 0..3 -> feats 4q..4q+3
    int half = l >> 2;    // head half: heads half*4 .. half*4+3
    const float4* hv = (const float4*)(g_ht + (size_t)src * 128);
    float4 acc = make_float4(0.f, 0.f, 0.f, 0.f);
#pragma unroll
    for (int hh = 0; hh < 4; hh++) {
        float a = __shfl_sync(0xffffffffu, alpha, half * 4 + hh, 8);
        float4 v = hv[(half * 4 + hh) * 4 + q];
        acc.x += a * v.x; acc.y += a * v.y; acc.z += a * v.z; acc.w += a * v.w;
    }
    // combine the two head-halves (lanes l and l^4 share the same quad q)
    acc.x += __shfl_xor_sync(0xffffffffu, acc.x, 4, 8);
    acc.y += __shfl_xor_sync(0xffffffffu, acc.y, 4, 8);
    acc.z += __shfl_xor_sync(0xffffffffu, acc.z, 4, 8);
    acc.w += __shfl_xor_sync(0xffffffffu, acc.w, 4, 8);
    if (half == 0) red_add_v4(out + (size_t)dst * 16 + q * 4, acc);
}

// ---------------------------------------------------------------------------
extern "C" void kernel_launch(void* const* d_in, const int* in_sizes, int n_in,
                              void* d_out, int out_size) {
    const float* h    = (const float*)d_in[0];
    const int*   ei   = (const int*)d_in[1];
    const float* ef   = (const float*)d_in[2];
    const float* Wn   = (const float*)d_in[3];
    const float* We   = (const float*)d_in[4];
    const float* asrc = (const float*)d_in[5];
    const float* adst = (const float*)d_in[6];
    float* out = (float*)d_out;

    const int SMEM = (128 * 128 + 32 * 128) * (int)sizeof(float);  // 80KB
    cudaFuncSetAttribute(k_gemm, cudaFuncAttributeMaxDynamicSharedMemorySize, SMEM);

    void* se_ptr = nullptr;
    cudaGetSymbolAddress(&se_ptr, g_se);
    cudaMemsetAsync(se_ptr, 0, (size_t)NN * 8 * sizeof(float));
    cudaMemsetAsync(out, 0, (size_t)NN * 16 * sizeof(float));

    k_gemm<<<296, 256, SMEM>>>(h, Wn);
    k_sdot<<<(NN * 8 + 255) / 256, 256>>>(asrc, adst);
    k_edgeA<<<EE / 256, 256>>>(ei, ef, We);
    k_edgeB<<<(EE * 8) / 256, 256>>>(ei, ef, We, out);
}

// round 3
// speedup vs baseline: 1.7661x; 1.7661x over previous
#include <cuda_runtime.h>

#define NN 50000
#define EE 800000

// Scratch (no cudaMalloc allowed)
__device__ float g_ht[NN * 128];   // h @ W_node, [N][H*F]
__device__ float g_ss[NN * 8];     // per-node src attention scalar, [N][H]
__device__ float g_sd[NN * 8];     // per-node dst attention scalar, [N][H]
__device__ float g_se[NN * 8];     // sum of exp per (dst, head)

__device__ __forceinline__ void red_add_v4(float* p, float4 v) {
    asm volatile("red.global.add.v4.f32 [%0], {%1,%2,%3,%4};"
                 :: "l"(p), "f"(v.x), "f"(v.y), "f"(v.z), "f"(v.w)
                 : "memory");
}

__device__ __forceinline__ unsigned long long pack2(float x, float y) {
    unsigned long long r;
    asm("mov.b64 %0, {%1, %2};" : "=l"(r) : "f"(x), "f"(y));
    return r;
}
__device__ __forceinline__ float2 unpack2(unsigned long long v) {
    float2 r;
    asm("mov.b64 {%0, %1}, %2;" : "=f"(r.x), "=f"(r.y) : "l"(v));
    return r;
}
// d = a * b + d  (packed 2 x fp32, Blackwell 2-wide FMA pipe)
__device__ __forceinline__ void fma2(unsigned long long& d,
                                     unsigned long long a,
                                     unsigned long long b) {
    asm("fma.rn.f32x2 %0, %1, %2, %0;" : "+l"(d) : "l"(a), "l"(b));
}

// ---------------------------------------------------------------------------
// K1: h_trans = h @ W_node via packed f32x2 FMA, fused s_src/s_dst epilogue.
// W (64KB) in SMEM as ulonglong2; h tile stored duplicated {h,h} (32KB).
// Tile: 32 nodes x 128 outputs. Thread: 4 nodes x 4 cols.
// ---------------------------------------------------------------------------
__global__ __launch_bounds__(256, 2) void k_gemm(const float* __restrict__ hin,
                                                 const float* __restrict__ Wn,
                                                 const float* __restrict__ asrc,
                                                 const float* __restrict__ adst) {
    extern __shared__ float sm[];
    float* Wsh = sm;                                          // 64KB
    unsigned long long* hsh2 =
        (unsigned long long*)(sm + 128 * 128);                // [32][128] u64 = 32KB

    const int tid = threadIdx.x;
    const float4* Wg = (const float4*)Wn;
    float4* Ws4 = (float4*)Wsh;
#pragma unroll
    for (int i = 0; i < 16; i++) Ws4[tid + i * 256] = Wg[tid + i * 256];

    const int tx = tid & 31;       // lane: cols 4*tx .. 4*tx+3
    const int ty = tid >> 5;       // node group: rows ty*4 .. ty*4+3
    const int head = tx >> 2;      // col 4tx+c -> head (4tx+c)>>4 = tx>>2
    const int part = tx & 3;       // feat quad within head
    const float4 va = ((const float4*)asrc)[head * 4 + part];
    const float4 vb = ((const float4*)adst)[head * 4 + part];

    const ulonglong2* Wsh2 = (const ulonglong2*)Wsh;
    const int ntiles = (NN + 31) >> 5;

    for (int tile = blockIdx.x; tile < ntiles; tile += gridDim.x) {
        const int n0 = tile << 5;
        __syncthreads();
#pragma unroll
        for (int i = 0; i < 4; i++) {
            int idx = tid + i * 256;       // float4 index == r*32 + c
            int r = idx >> 5, c = idx & 31;
            float4 v = make_float4(0.f, 0.f, 0.f, 0.f);
            if (n0 + r < NN) v = ((const float4*)hin)[(size_t)(n0 + r) * 32 + c];
            unsigned long long* hp = hsh2 + r * 128 + c * 4;
            hp[0] = pack2(v.x, v.x);
            hp[1] = pack2(v.y, v.y);
            hp[2] = pack2(v.z, v.z);
            hp[3] = pack2(v.w, v.w);
        }
        __syncthreads();

        unsigned long long a0 = 0, a1 = 0, a2 = 0, a3 = 0,
                           a4 = 0, a5 = 0, a6 = 0, a7 = 0;
        const unsigned long long* h0p = hsh2 + (ty * 4 + 0) * 128;
        const unsigned long long* h1p = hsh2 + (ty * 4 + 1) * 128;
        const unsigned long long* h2p = hsh2 + (ty * 4 + 2) * 128;
        const unsigned long long* h3p = hsh2 + (ty * 4 + 3) * 128;
#pragma unroll 8
        for (int k = 0; k < 128; k++) {
            ulonglong2 w = Wsh2[k * 32 + tx];
            unsigned long long h0 = h0p[k], h1 = h1p[k], h2 = h2p[k], h3 = h3p[k];
            fma2(a0, h0, w.x); fma2(a1, h0, w.y);
            fma2(a2, h1, w.x); fma2(a3, h1, w.y);
            fma2(a4, h2, w.x); fma2(a5, h2, w.y);
            fma2(a6, h3, w.x); fma2(a7, h3, w.y);
        }

        float4* op = (float4*)g_ht;
        unsigned long long accs[8] = {a0, a1, a2, a3, a4, a5, a6, a7};
#pragma unroll
        for (int j = 0; j < 4; j++) {
            int n = n0 + ty * 4 + j;
            float2 lo = unpack2(accs[2 * j]);
            float2 hi = unpack2(accs[2 * j + 1]);
            if (n < NN) op[n * 32 + tx] = make_float4(lo.x, lo.y, hi.x, hi.y);
            // fused attention scalars
            float ps = lo.x * va.x + lo.y * va.y + hi.x * va.z + hi.y * va.w;
            float pd = lo.x * vb.x + lo.y * vb.y + hi.x * vb.z + hi.y * vb.w;
            ps += __shfl_xor_sync(0xffffffffu, ps, 1);
            ps += __shfl_xor_sync(0xffffffffu, ps, 2);
            pd += __shfl_xor_sync(0xffffffffu, pd, 1);
            pd += __shfl_xor_sync(0xffffffffu, pd, 2);
            if (part == 0 && n < NN) {
                g_ss[n * 8 + head] = ps;
                g_sd[n * 8 + head] = pd;
            }
        }
    }
}

// ---------------------------------------------------------------------------
// K3: edge pass A — sum of exp(leaky_relu(logit)) per (dst, head).
// 2 threads/edge (4 heads each), 1 red.v4 per thread.
// (No segment-max needed: logits bounded, exp cannot overflow fp32, and
//  softmax is shift-invariant.)
// ---------------------------------------------------------------------------
__global__ void k_edgeA(const int* __restrict__ ei,
                        const float* __restrict__ ef,
                        const float* __restrict__ We) {
    int gid = blockIdx.x * 256 + threadIdx.x;   // grid exact: (EE*2) % 256 == 0
    int e = gid >> 1;
    int half = gid & 1;
    int src = ei[e];
    int dst = ei[EE + e];
    float f = __ldg(ef + e);
    float4 s = ((const float4*)g_ss)[src * 2 + half];
    float4 d = ((const float4*)g_sd)[dst * 2 + half];
    float4 w = ((const float4*)We)[half];
    float4 x;
    x.x = s.x + d.x + f * w.x;
    x.y = s.y + d.y + f * w.y;
    x.z = s.z + d.z + f * w.z;
    x.w = s.w + d.w + f * w.w;
    x.x = __expf(fmaxf(x.x, 0.2f * x.x));
    x.y = __expf(fmaxf(x.y, 0.2f * x.y));
    x.z = __expf(fmaxf(x.z, 0.2f * x.z));
    x.w = __expf(fmaxf(x.w, 0.2f * x.w));
    red_add_v4(g_se + dst * 8 + half * 4, x);
}

// ---------------------------------------------------------------------------
// K4: edge pass B — alpha = exp/sumexp (x 1/8 head-mean folded in), gather
// src features COALESCED, scatter weighted message into out[dst].
// 8 lanes/edge; lane l reads float4 j=i*8+l (iter i): warp-level 128B
// contiguous segments per edge. Head of element j is i*2+(l>>2); alpha
// broadcast via width-8 shfl. xor-4 combines complementary head sets.
// ---------------------------------------------------------------------------
__global__ void k_edgeB(const int* __restrict__ ei,
                        const float* __restrict__ ef,
                        const float* __restrict__ We,
                        float* __restrict__ out) {
    int gid = blockIdx.x * 256 + threadIdx.x;  // grid exact: (EE*8) % 256 == 0
    int e = gid >> 3;
    int l = gid & 7;
    int src = ei[e];
    int dst = ei[EE + e];

    // coalesced row gather: lanes 0-7 cover 128B contiguous per iter
    const float4* hv = (const float4*)(g_ht + (size_t)src * 128);
    float4 v0 = hv[l];
    float4 v1 = hv[8 + l];
    float4 v2 = hv[16 + l];
    float4 v3 = hv[24 + l];

    // this lane's head-l alpha
    float f = __ldg(ef + e);
    float s = g_ss[src * 8 + l] + g_sd[dst * 8 + l] + f * __ldg(We + l);
    s = fmaxf(s, 0.2f * s);
    float alpha = 0.125f * __expf(s) / g_se[dst * 8 + l];

    int hi = l >> 2;   // element j = i*8+l has head i*2 + hi, quad l&3
    float4 acc;
    float a;
    a = __shfl_sync(0xffffffffu, alpha, 0 + hi, 8);
    acc.x = a * v0.x; acc.y = a * v0.y; acc.z = a * v0.z; acc.w = a * v0.w;
    a = __shfl_sync(0xffffffffu, alpha, 2 + hi, 8);
    acc.x += a * v1.x; acc.y += a * v1.y; acc.z += a * v1.z; acc.w += a * v1.w;
    a = __shfl_sync(0xffffffffu, alpha, 4 + hi, 8);
    acc.x += a * v2.x; acc.y += a * v2.y; acc.z += a * v2.z; acc.w += a * v2.w;
    a = __shfl_sync(0xffffffffu, alpha, 6 + hi, 8);
    acc.x += a * v3.x; acc.y += a * v3.y; acc.z += a * v3.z; acc.w += a * v3.w;

    // lanes l and l^4 hold the same quad over complementary head sets
    acc.x += __shfl_xor_sync(0xffffffffu, acc.x, 4, 8);
    acc.y += __shfl_xor_sync(0xffffffffu, acc.y, 4, 8);
    acc.z += __shfl_xor_sync(0xffffffffu, acc.z, 4, 8);
    acc.w += __shfl_xor_sync(0xffffffffu, acc.w, 4, 8);
    if (hi == 0) red_add_v4(out + (size_t)dst * 16 + l * 4, acc);
}

// ---------------------------------------------------------------------------
extern "C" void kernel_launch(void* const* d_in, const int* in_sizes, int n_in,
                              void* d_out, int out_size) {
    const float* h    = (const float*)d_in[0];
    const int*   ei   = (const int*)d_in[1];
    const float* ef   = (const float*)d_in[2];
    const float* Wn   = (const float*)d_in[3];
    const float* We   = (const float*)d_in[4];
    const float* asrc = (const float*)d_in[5];
    const float* adst = (const float*)d_in[6];
    float* out = (float*)d_out;

    const int SMEM = 128 * 128 * 4 + 32 * 128 * 8;  // 64KB W + 32KB packed h = 96KB
    cudaFuncSetAttribute(k_gemm, cudaFuncAttributeMaxDynamicSharedMemorySize, SMEM);

    void* se_ptr = nullptr;
    cudaGetSymbolAddress(&se_ptr, g_se);
    cudaMemsetAsync(se_ptr, 0, (size_t)NN * 8 * sizeof(float));
    cudaMemsetAsync(out, 0, (size_t)NN * 16 * sizeof(float));

    k_gemm<<<296, 256, SMEM>>>(h, Wn, asrc, adst);
    k_edgeA<<<(EE * 2) / 256, 256>>>(ei, ef, We);
    k_edgeB<<<(EE * 8) / 256, 256>>>(ei, ef, We, out);
}

// round 4
// speedup vs baseline: 1.8005x; 1.0195x over previous
#include <cuda_runtime.h>

#define NN 50000
#define EE 800000

// Scratch (no cudaMalloc allowed)
__device__ float g_ht[NN * 128];   // h @ W_node, [N][H*F]
__device__ float g_ss[NN * 8];     // per-node src attention scalar, [N][H]
__device__ float g_sd[NN * 8];     // per-node dst attention scalar, [N][H]
__device__ float g_se[NN * 8];     // sum of exp per (dst, head)

__device__ __forceinline__ void red_add_v4(float* p, float4 v) {
    asm volatile("red.global.add.v4.f32 [%0], {%1,%2,%3,%4};"
                 :: "l"(p), "f"(v.x), "f"(v.y), "f"(v.z), "f"(v.w)
                 : "memory");
}

__device__ __forceinline__ unsigned long long pack2(float x, float y) {
    unsigned long long r;
    asm("mov.b64 %0, {%1, %2};" : "=l"(r) : "f"(x), "f"(y));
    return r;
}
__device__ __forceinline__ float2 unpack2(unsigned long long v) {
    float2 r;
    asm("mov.b64 {%0, %1}, %2;" : "=f"(r.x), "=f"(r.y) : "l"(v));
    return r;
}
// d = a * b + d  (packed 2 x fp32)
__device__ __forceinline__ void fma2(unsigned long long& d,
                                     unsigned long long a,
                                     unsigned long long b) {
    asm("fma.rn.f32x2 %0, %1, %2, %0;" : "+l"(d) : "l"(a), "l"(b));
}

// ---------------------------------------------------------------------------
// K1: h_trans = h @ W_node via K-PAIRED packed f32x2 FMA + fused s_src/s_dst.
//   acc u64 = {sum over even k, sum over odd k};  col value = lo + hi.
//   W in SMEM as u64 {W[2kp][c], W[2kp+1][c]}  -> [64 kp][128 c]  (64KB)
//   h tile in SMEM as raw rows (u64 view = natural k-pairs)        (32KB)
// Tile: 64 nodes x 128 cols. Thread: 8 nodes x 4 cols (32 u64 accs).
// ---------------------------------------------------------------------------
__global__ __launch_bounds__(256, 2) void k_gemm(const float* __restrict__ hin,
                                                 const float* __restrict__ Wn,
                                                 const float* __restrict__ asrc,
                                                 const float* __restrict__ adst) {
    extern __shared__ float sm[];
    unsigned long long* Wsh = (unsigned long long*)sm;            // [64][128] u64
    unsigned long long* hsh = (unsigned long long*)(sm + 128 * 128); // [64][64] u64

    const int tid = threadIdx.x;

    // Pack W: Wsh[kp*128 + c] = {W[2kp][c], W[2kp+1][c]}
    {
        const float4* W4 = (const float4*)Wn;
#pragma unroll
        for (int i = 0; i < 8; i++) {
            int idx = tid + i * 256;        // 2048 = 64 kp * 32 col-groups
            int kp = idx >> 5, cg = idx & 31;
            float4 a = W4[(2 * kp) * 32 + cg];
            float4 b = W4[(2 * kp + 1) * 32 + cg];
            unsigned long long* wp = Wsh + kp * 128 + cg * 4;
            wp[0] = pack2(a.x, b.x);
            wp[1] = pack2(a.y, b.y);
            wp[2] = pack2(a.z, b.z);
            wp[3] = pack2(a.w, b.w);
        }
    }

    const int tx = tid & 31;       // lane: cols 4*tx .. 4*tx+3
    const int ty = tid >> 5;       // warp: nodes ty*8 .. ty*8+7
    const int head = tx >> 2;
    const int part = tx & 3;
    const float4 va = ((const float4*)asrc)[head * 4 + part];
    const float4 vb = ((const float4*)adst)[head * 4 + part];

    const ulonglong2* Wv2 = (const ulonglong2*)Wsh;  // [kp][64 pairs]
    const int ntiles = (NN + 63) >> 6;

    for (int tile = blockIdx.x; tile < ntiles; tile += gridDim.x) {
        const int n0 = tile << 6;
        __syncthreads();
        // load 64 node rows (raw; u64 view gives k-pairs)
#pragma unroll
        for (int i = 0; i < 8; i++) {
            int idx = tid + i * 256;        // 2048 = 64 rows * 32 float4
            int r = idx >> 5, c = idx & 31;
            float4 v = make_float4(0.f, 0.f, 0.f, 0.f);
            if (n0 + r < NN) v = ((const float4*)hin)[(size_t)(n0 + r) * 32 + c];
            ((float4*)hsh)[idx] = v;
        }
        __syncthreads();

        unsigned long long acc[8][2];   // [node][col-pair as ulonglong2 halves]
        unsigned long long acc2[8][2];
#pragma unroll
        for (int j = 0; j < 8; j++) {
            acc[j][0] = 0; acc[j][1] = 0; acc2[j][0] = 0; acc2[j][1] = 0;
        }
        const unsigned long long* hrow = hsh + (size_t)(ty * 8) * 64;

#pragma unroll 4
        for (int kp = 0; kp < 64; kp++) {
            ulonglong2 w01 = Wv2[kp * 64 + tx * 2];       // cols 4tx, 4tx+1
            ulonglong2 w23 = Wv2[kp * 64 + tx * 2 + 1];   // cols 4tx+2, 4tx+3
#pragma unroll
            for (int j = 0; j < 8; j++) {
                unsigned long long hk = hrow[j * 64 + kp];
                fma2(acc[j][0], hk, w01.x);
                fma2(acc[j][1], hk, w01.y);
                fma2(acc2[j][0], hk, w23.x);
                fma2(acc2[j][1], hk, w23.y);
            }
        }

        float4* op = (float4*)g_ht;
#pragma unroll
        for (int j = 0; j < 8; j++) {
            int n = n0 + ty * 8 + j;
            float2 c0 = unpack2(acc[j][0]);
            float2 c1 = unpack2(acc[j][1]);
            float2 c2 = unpack2(acc2[j][0]);
            float2 c3 = unpack2(acc2[j][1]);
            float4 r = make_float4(c0.x + c0.y, c1.x + c1.y,
                                   c2.x + c2.y, c3.x + c3.y);
            if (n < NN) op[n * 32 + tx] = r;
            // fused attention scalars
            float ps = r.x * va.x + r.y * va.y + r.z * va.z + r.w * va.w;
            float pd = r.x * vb.x + r.y * vb.y + r.z * vb.z + r.w * vb.w;
            ps += __shfl_xor_sync(0xffffffffu, ps, 1);
            ps += __shfl_xor_sync(0xffffffffu, ps, 2);
            pd += __shfl_xor_sync(0xffffffffu, pd, 1);
            pd += __shfl_xor_sync(0xffffffffu, pd, 2);
            if (part == 0 && n < NN) {
                g_ss[n * 8 + head] = ps;
                g_sd[n * 8 + head] = pd;
            }
        }
    }
}

// ---------------------------------------------------------------------------
// K3: edge pass A — sum of exp(leaky_relu(logit)) per (dst, head).
// 2 threads/edge (4 heads each), 1 red.v4 per thread.
// ---------------------------------------------------------------------------
__global__ void k_edgeA(const int* __restrict__ ei,
                        const float* __restrict__ ef,
                        const float* __restrict__ We) {
    int gid = blockIdx.x * 256 + threadIdx.x;   // grid exact: (EE*2) % 256 == 0
    int e = gid >> 1;
    int half = gid & 1;
    int src = ei[e];
    int dst = ei[EE + e];
    float f = __ldg(ef + e);
    float4 s = ((const float4*)g_ss)[src * 2 + half];
    float4 d = ((const float4*)g_sd)[dst * 2 + half];
    float4 w = ((const float4*)We)[half];
    float4 x;
    x.x = s.x + d.x + f * w.x;
    x.y = s.y + d.y + f * w.y;
    x.z = s.z + d.z + f * w.z;
    x.w = s.w + d.w + f * w.w;
    x.x = __expf(fmaxf(x.x, 0.2f * x.x));
    x.y = __expf(fmaxf(x.y, 0.2f * x.y));
    x.z = __expf(fmaxf(x.z, 0.2f * x.z));
    x.w = __expf(fmaxf(x.w, 0.2f * x.w));
    red_add_v4(g_se + dst * 8 + half * 4, x);
}

// ---------------------------------------------------------------------------
// K4: edge pass B — alpha = exp/sumexp (x 1/8 head-mean folded), coalesced
// gather of h_trans[src], scatter weighted message to out[dst].
// ---------------------------------------------------------------------------
__global__ void k_edgeB(const int* __restrict__ ei,
                        const float* __restrict__ ef,
                        const float* __restrict__ We,
                        float* __restrict__ out) {
    int gid = blockIdx.x * 256 + threadIdx.x;  // grid exact: (EE*8) % 256 == 0
    int e = gid >> 3;
    int l = gid & 7;
    int src = ei[e];
    int dst = ei[EE + e];

    // coalesced row gather: lanes 0-7 cover 128B contiguous per iter
    const float4* hv = (const float4*)(g_ht + (size_t)src * 128);
    float4 v0 = hv[l];
    float4 v1 = hv[8 + l];
    float4 v2 = hv[16 + l];
    float4 v3 = hv[24 + l];

    // this lane's head-l alpha
    float f = __ldg(ef + e);
    float s = g_ss[src * 8 + l] + g_sd[dst * 8 + l] + f * __ldg(We + l);
    s = fmaxf(s, 0.2f * s);
    float alpha = 0.125f * __expf(s) / g_se[dst * 8 + l];

    int hi = l >> 2;   // element j = i*8+l has head i*2 + hi, quad l&3
    float4 acc;
    float a;
    a = __shfl_sync(0xffffffffu, alpha, 0 + hi, 8);
    acc.x = a * v0.x; acc.y = a * v0.y; acc.z = a * v0.z; acc.w = a * v0.w;
    a = __shfl_sync(0xffffffffu, alpha, 2 + hi, 8);
    acc.x += a * v1.x; acc.y += a * v1.y; acc.z += a * v1.z; acc.w += a * v1.w;
    a = __shfl_sync(0xffffffffu, alpha, 4 + hi, 8);
    acc.x += a * v2.x; acc.y += a * v2.y; acc.z += a * v2.z; acc.w += a * v2.w;
    a = __shfl_sync(0xffffffffu, alpha, 6 + hi, 8);
    acc.x += a * v3.x; acc.y += a * v3.y; acc.z += a * v3.z; acc.w += a * v3.w;

    // lanes l and l^4 hold the same quad over complementary head sets
    acc.x += __shfl_xor_sync(0xffffffffu, acc.x, 4, 8);
    acc.y += __shfl_xor_sync(0xffffffffu, acc.y, 4, 8);
    acc.z += __shfl_xor_sync(0xffffffffu, acc.z, 4, 8);
    acc.w += __shfl_xor_sync(0xffffffffu, acc.w, 4, 8);
    if (hi == 0) red_add_v4(out + (size_t)dst * 16 + l * 4, acc);
}

// ---------------------------------------------------------------------------
extern "C" void kernel_launch(void* const* d_in, const int* in_sizes, int n_in,
                              void* d_out, int out_size) {
    const float* h    = (const float*)d_in[0];
    const int*   ei   = (const int*)d_in[1];
    const float* ef   = (const float*)d_in[2];
    const float* Wn   = (const float*)d_in[3];
    const float* We   = (const float*)d_in[4];
    const float* asrc = (const float*)d_in[5];
    const float* adst = (const float*)d_in[6];
    float* out = (float*)d_out;

    const int SMEM = 128 * 128 * 4 + 64 * 64 * 8;  // 64KB packed W + 32KB h = 96KB
    cudaFuncSetAttribute(k_gemm, cudaFuncAttributeMaxDynamicSharedMemorySize, SMEM);

    void* se_ptr = nullptr;
    cudaGetSymbolAddress(&se_ptr, g_se);
    cudaMemsetAsync(se_ptr, 0, (size_t)NN * 8 * sizeof(float));
    cudaMemsetAsync(out, 0, (size_t)NN * 16 * sizeof(float));

    k_gemm<<<296, 256, SMEM>>>(h, Wn, asrc, adst);
    k_edgeA<<<(EE * 2) / 256, 256>>>(ei, ef, We);
    k_edgeB<<<(EE * 8) / 256, 256>>>(ei, ef, We, out);
}

// round 7
// speedup vs baseline: 2.2304x; 1.2388x over previous
#include <cuda_runtime.h>
#include <cuda_bf16.h>

#define NN 50000
#define EE 800000

// Scratch (no cudaMalloc allowed)
__device__ float g_ht[NN * 128];   // h @ W_node, [N][H*F]
__device__ float g_ss[NN * 8];     // per-node src attention scalar
__device__ float g_sd[NN * 8];     // per-node dst attention scalar
__device__ float g_se[NN * 8];     // sum of exp per (dst, head)
__device__ uint4 g_Bhi[2048];      // W^T hi bf16, [n=128][k=128] (32KB)
__device__ uint4 g_Blo[2048];      // W^T lo bf16

// ---------------- helpers ----------------
__device__ __forceinline__ void red_add_v4(float* p, float4 v) {
    asm volatile("red.global.add.v4.f32 [%0], {%1,%2,%3,%4};"
                 :: "l"(p), "f"(v.x), "f"(v.y), "f"(v.z), "f"(v.w) : "memory");
}
__device__ __forceinline__ unsigned smem_u32(const void* p) {
    unsigned a;
    asm("{ .reg .u64 t; cvta.to.shared.u64 t, %1; cvt.u32.u64 %0, t; }"
        : "=r"(a) : "l"(p));
    return a;
}
__device__ __forceinline__ void ldsm4(unsigned* r, unsigned addr) {
    asm volatile("ldmatrix.sync.aligned.m8n8.x4.shared.b16 {%0,%1,%2,%3}, [%4];"
                 : "=r"(r[0]), "=r"(r[1]), "=r"(r[2]), "=r"(r[3]) : "r"(addr));
}
__device__ __forceinline__ void mma_bf16(float* d, const unsigned* a,
                                         unsigned b0, unsigned b1) {
    asm volatile(
        "mma.sync.aligned.m16n8k16.row.col.f32.bf16.bf16.f32 "
        "{%0,%1,%2,%3}, {%4,%5,%6,%7}, {%8,%9}, {%0,%1,%2,%3};"
        : "+f"(d[0]), "+f"(d[1]), "+f"(d[2]), "+f"(d[3])
        : "r"(a[0]), "r"(a[1]), "r"(a[2]), "r"(a[3]), "r"(b0), "r"(b1));
}
// 16B-chunk swizzle within a 256B row: chunk c (0..15), row r
__device__ __forceinline__ int swz(int c, int r) {
    return (c & 8) | ((c ^ r) & 7);
}

// ---------------------------------------------------------------------------
// K0: prepack W^T hi/lo bf16 (plain [n][k] layout). B[n][k] = W[k][n].
// ---------------------------------------------------------------------------
__global__ void k_prepW(const float* __restrict__ Wn) {
    int idx = blockIdx.x * 256 + threadIdx.x;
    if (idx >= 128 * 128) return;
    int n = idx >> 7, k = idx & 127;
    float v = Wn[k * 128 + n];
    __nv_bfloat16 hi = __float2bfloat16(v);
    __nv_bfloat16 lo = __float2bfloat16(v - __bfloat162float(hi));
    ((__nv_bfloat16*)g_Bhi)[n * 128 + k] = hi;
    ((__nv_bfloat16*)g_Blo)[n * 128 + k] = lo;
}

// ---------------------------------------------------------------------------
// K1: bf16 3-term GEMM via mma.sync (HMMA). D = Ahi*Bhi + Ahi*Blo + Alo*Bhi.
// CTA tile: 64 nodes x 128 cols. 8 warps: warp = (rh = row quarter of 16,
// ch = col half of 64). SMEM bf16 tiles, 256B rows, XOR-16B swizzle.
// ---------------------------------------------------------------------------
#define SM_AHI 0
#define SM_ALO 16384
#define SM_BHI 32768
#define SM_BLO 65536
#define SM_TOT 98304

__global__ __launch_bounds__(256, 2) void k_gemm(const float* __restrict__ hin) {
    extern __shared__ char sm[];
    const unsigned sb = smem_u32(sm);
    const int tid = threadIdx.x, wid = tid >> 5, lid = tid & 31;
    const int n0 = blockIdx.x << 6;

    // --- fill B tiles (copy 16B chunks with swizzle) ---
#pragma unroll
    for (int i = 0; i < 8; i++) {
        int idx = tid + i * 256;           // 2048 = 128 rows x 16 chunks
        int r = idx >> 4, c = idx & 15;
        int off = r * 256 + swz(c, r & 7) * 16;
        *(uint4*)(sm + SM_BHI + off) = g_Bhi[idx];
        *(uint4*)(sm + SM_BLO + off) = g_Blo[idx];
    }
    // --- fill A tiles: load fp32 h rows, split hi/lo bf16, swizzled store ---
    const float4* h4 = (const float4*)hin;
#pragma unroll
    for (int i = 0; i < 8; i++) {
        int idx = tid + i * 256;           // 2048 = 64 rows x 32 float4
        int r = idx >> 5, c4 = idx & 31;
        int k = c4 << 2;
        float4 v = make_float4(0.f, 0.f, 0.f, 0.f);
        if (n0 + r < NN) v = h4[(size_t)(n0 + r) * 32 + c4];
        __nv_bfloat162 hA = __floats2bfloat162_rn(v.x, v.y);
        __nv_bfloat162 hB = __floats2bfloat162_rn(v.z, v.w);
        __nv_bfloat162 lA = __floats2bfloat162_rn(v.x - __bfloat162float(hA.x),
                                                  v.y - __bfloat162float(hA.y));
        __nv_bfloat162 lB = __floats2bfloat162_rn(v.z - __bfloat162float(hB.x),
                                                  v.w - __bfloat162float(hB.y));
        int off = r * 256 + swz(k >> 3, r & 7) * 16 + (k & 7) * 2;
        *(uint2*)(sm + SM_AHI + off) = make_uint2(*(unsigned*)&hA, *(unsigned*)&hB);
        *(uint2*)(sm + SM_ALO + off) = make_uint2(*(unsigned*)&lA, *(unsigned*)&lB);
    }
    __syncthreads();

    const int rh = wid & 3;     // rows rh*16 .. rh*16+15
    const int ch = wid >> 2;    // cols ch*64 .. ch*64+63

    float acc[8][4];
#pragma unroll
    for (int t = 0; t < 8; t++)
#pragma unroll
        for (int j = 0; j < 4; j++) acc[t][j] = 0.f;

    // A ldmatrix lane address pieces (row = rh*16 + (lid&15), chunk +(lid>>4))
    const int arow = rh * 16 + (lid & 15);
    // B lane address pieces
    const int bl = (lid & 7) + ((lid >> 4) << 3);   // row-within-16 for x4
    const int bko = (lid >> 3) & 1;                 // k-chunk parity

#pragma unroll
    for (int ks = 0; ks < 8; ks++) {
        unsigned ahi[4], alo[4];
        {
            int c = ks * 2 + (lid >> 4);
            int aoff = arow * 256 + swz(c, arow & 7) * 16;
            ldsm4(ahi, sb + SM_AHI + aoff);
            ldsm4(alo, sb + SM_ALO + aoff);
        }
#pragma unroll
        for (int p = 0; p < 4; p++) {       // 4 n-pairs of 16 cols
            int n = ch * 64 + p * 16 + bl;
            int c = ks * 2 + bko;
            int boff = n * 256 + swz(c, n & 7) * 16;
            unsigned bhi[4], blo[4];
            ldsm4(bhi, sb + SM_BHI + boff);
            ldsm4(blo, sb + SM_BLO + boff);
            mma_bf16(acc[2 * p],     ahi, bhi[0], bhi[1]);
            mma_bf16(acc[2 * p],     ahi, blo[0], blo[1]);
            mma_bf16(acc[2 * p],     alo, bhi[0], bhi[1]);
            mma_bf16(acc[2 * p + 1], ahi, bhi[2], bhi[3]);
            mma_bf16(acc[2 * p + 1], ahi, blo[2], blo[3]);
            mma_bf16(acc[2 * p + 1], alo, bhi[2], bhi[3]);
        }
    }

    // --- epilogue: write g_ht ---
    const int r0 = n0 + rh * 16 + (lid >> 2);
    const int r1 = r0 + 8;
#pragma unroll
    for (int t = 0; t < 8; t++) {
        int gcol = ch * 64 + t * 8 + 2 * (lid & 3);
        if (r0 < NN) *(float2*)(g_ht + (size_t)r0 * 128 + gcol) =
            make_float2(acc[t][0], acc[t][1]);
        if (r1 < NN) *(float2*)(g_ht + (size_t)r1 * 128 + gcol) =
            make_float2(acc[t][2], acc[t][3]);
    }
}

// ---------------------------------------------------------------------------
// K2: per-node attention scalars.
// ---------------------------------------------------------------------------
__global__ void k_sdot(const float* __restrict__ asrc,
                       const float* __restrict__ adst) {
    int t = blockIdx.x * blockDim.x + threadIdx.x;
    if (t >= NN * 8) return;
    int n = t >> 3, hh = t & 7;
    const float4* hp = (const float4*)(g_ht + (size_t)n * 128 + hh * 16);
    const float4* as = (const float4*)(asrc + hh * 16);
    const float4* ad = (const float4*)(adst + hh * 16);
    float ss = 0.f, sd = 0.f;
#pragma unroll
    for (int i = 0; i < 4; i++) {
        float4 v = hp[i];
        float4 a = __ldg(as + i);
        float4 b = __ldg(ad + i);
        ss += v.x * a.x + v.y * a.y + v.z * a.z + v.w * a.w;
        sd += v.x * b.x + v.y * b.y + v.z * b.z + v.w * b.w;
    }
    g_ss[t] = ss;
    g_sd[t] = sd;
}

// ---------------------------------------------------------------------------
// K3: edge pass A — sum of exp(leaky_relu(logit)) per (dst, head).
// ---------------------------------------------------------------------------
__global__ void k_edgeA(const int* __restrict__ ei,
                        const float* __restrict__ ef,
                        const float* __restrict__ We) {
    int gid = blockIdx.x * 256 + threadIdx.x;   // grid exact: (EE*2) % 256 == 0
    int e = gid >> 1;
    int half = gid & 1;
    int src = ei[e];
    int dst = ei[EE + e];
    float f = __ldg(ef + e);
    float4 s = ((const float4*)g_ss)[src * 2 + half];
    float4 d = ((const float4*)g_sd)[dst * 2 + half];
    float4 w = ((const float4*)We)[half];
    float4 x;
    x.x = s.x + d.x + f * w.x;
    x.y = s.y + d.y + f * w.y;
    x.z = s.z + d.z + f * w.z;
    x.w = s.w + d.w + f * w.w;
    x.x = __expf(fmaxf(x.x, 0.2f * x.x));
    x.y = __expf(fmaxf(x.y, 0.2f * x.y));
    x.z = __expf(fmaxf(x.z, 0.2f * x.z));
    x.w = __expf(fmaxf(x.w, 0.2f * x.w));
    red_add_v4(g_se + dst * 8 + half * 4, x);
}

// ---------------------------------------------------------------------------
// K4: edge pass B — alpha-weighted gather/scatter (coalesced), mean folded.
// ---------------------------------------------------------------------------
__global__ void k_edgeB(const int* __restrict__ ei,
                        const float* __restrict__ ef,
                        const float* __restrict__ We,
                        float* __restrict__ out) {
    int gid = blockIdx.x * 256 + threadIdx.x;  // grid exact: (EE*8) % 256 == 0
    int e = gid >> 3;
    int l = gid & 7;
    int src = ei[e];
    int dst = ei[EE + e];

    const float4* hv = (const float4*)(g_ht + (size_t)src * 128);
    float4 v0 = hv[l];
    float4 v1 = hv[8 + l];
    float4 v2 = hv[16 + l];
    float4 v3 = hv[24 + l];

    float f = __ldg(ef + e);
    float s = g_ss[src * 8 + l] + g_sd[dst * 8 + l] + f * __ldg(We + l);
    s = fmaxf(s, 0.2f * s);
    float alpha = 0.125f * __expf(s) / g_se[dst * 8 + l];

    int hi = l >> 2;
    float4 acc;
    float a;
    a = __shfl_sync(0xffffffffu, alpha, 0 + hi, 8);
    acc.x = a * v0.x; acc.y = a * v0.y; acc.z = a * v0.z; acc.w = a * v0.w;
    a = __shfl_sync(0xffffffffu, alpha, 2 + hi, 8);
    acc.x += a * v1.x; acc.y += a * v1.y; acc.z += a * v1.z; acc.w += a * v1.w;
    a = __shfl_sync(0xffffffffu, alpha, 4 + hi, 8);
    acc.x += a * v2.x; acc.y += a * v2.y; acc.z += a * v2.z; acc.w += a * v2.w;
    a = __shfl_sync(0xffffffffu, alpha, 6 + hi, 8);
    acc.x += a * v3.x; acc.y += a * v3.y; acc.z += a * v3.z; acc.w += a * v3.w;

    acc.x += __shfl_xor_sync(0xffffffffu, acc.x, 4, 8);
    acc.y += __shfl_xor_sync(0xffffffffu, acc.y, 4, 8);
    acc.z += __shfl_xor_sync(0xffffffffu, acc.z, 4, 8);
    acc.w += __shfl_xor_sync(0xffffffffu, acc.w, 4, 8);
    if (hi == 0) red_add_v4(out + (size_t)dst * 16 + l * 4, acc);
}

// ---------------------------------------------------------------------------
extern "C" void kernel_launch(void* const* d_in, const int* in_sizes, int n_in,
                              void* d_out, int out_size) {
    const float* h    = (const float*)d_in[0];
    const int*   ei   = (const int*)d_in[1];
    const float* ef   = (const float*)d_in[2];
    const float* Wn   = (const float*)d_in[3];
    const float* We   = (const float*)d_in[4];
    const float* asrc = (const float*)d_in[5];
    const float* adst = (const float*)d_in[6];
    float* out = (float*)d_out;

    cudaFuncSetAttribute(k_gemm, cudaFuncAttributeMaxDynamicSharedMemorySize, SM_TOT);

    void* se_ptr = nullptr;
    cudaGetSymbolAddress(&se_ptr, g_se);
    cudaMemsetAsync(se_ptr, 0, (size_t)NN * 8 * sizeof(float));
    cudaMemsetAsync(out, 0, (size_t)NN * 16 * sizeof(float));

    k_prepW<<<64, 256>>>(Wn);
    k_gemm<<<(NN + 63) / 64, 256, SM_TOT>>>(h);
    k_sdot<<<(NN * 8 + 255) / 256, 256>>>(asrc, adst);
    k_edgeA<<<(EE * 2) / 256, 256>>>(ei, ef, We);
    k_edgeB<<<(EE * 8) / 256, 256>>>(ei, ef, We, out);
}